// round 11
// baseline (speedup 1.0000x reference)
#include <cuda_runtime.h>
#include <cstdint>

#define VOCAB  8000
#define VPAD   8192               // g_Wo rows padded to multiple of 256 (zero-filled)
#define HIDDEN 256
#define BATCH  32
#define SEQ    256
#define NROW   (SEQ * BATCH)      // 8192 output rows

// ---------------- scratch (device globals: allocation-free) ----------------
__device__ float g_Xp[NROW * HIDDEN];    // gathered emb + b_ih + b_hh
__device__ float g_Y [NROW * HIDDEN];    // RNN hidden outputs (tf32-rounded)
__device__ float g_Wo[VPAD * HIDDEN];    // W_out pre-rounded to tf32, zero-padded
__device__ float g_hlast[BATCH * HIDDEN];// exact fp32 final hidden state
__device__ unsigned int g_prog[BATCH];   // per-batch completed-step counter

extern __shared__ unsigned char dynsm[];

// ---------------- helpers ----------------
__device__ __forceinline__ uint32_t smem_u32(const void* p) {
    uint32_t a;
    asm("{ .reg .u64 t; cvta.to.shared.u64 t, %1; cvt.u32.u64 %0, t; }"
        : "=r"(a) : "l"(p));
    return a;
}
__device__ __forceinline__ uint32_t f2tf32(float f) {
    uint32_t r; asm("cvt.rna.tf32.f32 %0, %1;" : "=r"(r) : "f"(f)); return r;
}
__device__ __forceinline__ void fma2(uint64_t& d, uint64_t a, uint64_t b) {
    asm("fma.rn.f32x2 %0, %1, %2, %0;" : "+l"(d) : "l"(a), "l"(b));
}
__device__ __forceinline__ float lo32(uint64_t v) { return __uint_as_float((uint32_t)v); }
__device__ __forceinline__ float hi32(uint64_t v) { return __uint_as_float((uint32_t)(v >> 32)); }
__device__ __forceinline__ void cpa16(uint32_t dst, const void* src) {
    asm volatile("cp.async.cg.shared.global [%0], [%1], 16;" :: "r"(dst), "l"(src));
}
__device__ __forceinline__ unsigned int ld_acq(const unsigned int* p) {
    unsigned int v;
    asm volatile("ld.acquire.gpu.u32 %0, [%1];" : "=r"(v) : "l"(p) : "memory");
    return v;
}
__device__ __forceinline__ void st_rlx(unsigned int* p, unsigned int v) {
    asm volatile("st.relaxed.gpu.u32 [%0], %1;" :: "l"(p), "r"(v) : "memory");
}

// ---------------- K1: fused prep ----------------
// Blocks 0..8191: gather. Block r (= s*BATCH+b) computes
//   Xp[r][i] = W_ih[i][X[b][s]] + b_ih[i] + b_hh[i]   (i = threadIdx.x)
//   (direct scattered read of W_ih column v: 1 sector/lane, ~15us total; no transpose)
// Blocks 8192..10239: pre-round W_out to tf32 into g_Wo (zero-pad rows >= VOCAB).
__global__ void __launch_bounds__(256)
prep(const int* __restrict__ X, const float* __restrict__ Wih,
     const float* __restrict__ b_ih, const float* __restrict__ b_hh,
     const float* __restrict__ Wout) {
    const int t = threadIdx.x;
    if (blockIdx.x < NROW) {
        const int r = blockIdx.x;
        if (r == 0 && t < BATCH) g_prog[t] = 0;
        const int s = r >> 5, b = r & 31;
        const int v = X[b * SEQ + s];                 // broadcast load
        float e = Wih[(size_t)t * VOCAB + v] + b_ih[t] + b_hh[t];
        g_Xp[(size_t)r * HIDDEN + t] = e;
    } else {
        int i = (blockIdx.x - NROW) * 256 + t;        // over VPAD*64 float4s
        int row = i >> 6;
        uint4 u = make_uint4(0u, 0u, 0u, 0u);
        if (row < VOCAB) {
            float4 f = ((const float4*)Wout)[i];
            u = make_uint4(f2tf32(f.x), f2tf32(f.y), f2tf32(f.z), f2tf32(f.w));
        }
        ((uint4*)g_Wo)[i] = u;
    }
}

// ---------------- K2: FUSED scan + GEMM (persistent overlap) ----------------
// Blocks 0..31: rnn scan (scan6, proven 264us) for batch b = blockIdx.x,
//   publishing g_prog[b] = s+1 every 4 steps.
// Blocks 32..2079: GEMM BM128 x BN256, row-tile-major (rTile = g>>5), warp
//   tile 32x32 (4Mx8N warps) -> 0.5 mma per LDS-wavefront (R10's 32x16 tile
//   was 0.33 -> LDS-bound consumer, the reason overlap under-delivered).
#define WSTR      260
#define HB_OFF    (128 * WSTR)                  // hbuf: [2][256]
#define PART_OFF  (HB_OFF + 512)                // part: [16][132]
#define XBUF_OFF  (PART_OFF + 2112)             // xbuf: [256]
#define FUSED_SMEM ((XBUF_OFF + 256) * 4)       // 144,640 B

#define GSTG  (128 * 36 + 256 * 36)             // 13824 u32 per stage (55.3KB; x2 = 110.6KB)

__device__ __forceinline__ void mma_tf32(float* d, const uint32_t* a, const uint32_t* b) {
    asm volatile(
        "mma.sync.aligned.m16n8k8.row.col.f32.tf32.tf32.f32 "
        "{%0,%1,%2,%3}, {%4,%5,%6,%7}, {%8,%9}, {%0,%1,%2,%3};"
        : "+f"(d[0]), "+f"(d[1]), "+f"(d[2]), "+f"(d[3])
        : "r"(a[0]), "r"(a[1]), "r"(a[2]), "r"(a[3]), "r"(b[0]), "r"(b[1]));
}

__global__ void __launch_bounds__(1024, 1)
fused_scan_gemm(const float* __restrict__ Whh, const float* __restrict__ h0,
                const float* __restrict__ bout, float* __restrict__ out) {
    const int t = threadIdx.x;

    if (blockIdx.x < 32) {
        // ================= scan (scan6 verbatim) =================
        float* Ws   = (float*)dynsm;          // [128][260]
        float* hbuf = Ws + HB_OFF;
        float* part = Ws + PART_OFF;
        float* xbuf = Ws + XBUF_OFF;

        const int b = blockIdx.x;
        const int o = t & 127;
        const int p = t >> 7;

        for (int i = t; i < 128 * 256; i += 1024) {
            int r = i >> 8, c = i & 255;
            Ws[r * WSTR + c] = Whh[r * 256 + c];
        }
        ulonglong2 wr[8];
        {
            const ulonglong2* wsrc = (const ulonglong2*)(Whh + (size_t)(128 + o) * 256 + p * 32);
            #pragma unroll
            for (int i = 0; i < 8; i++) wr[i] = wsrc[i];
        }
        if (t < 256) hbuf[t] = h0[b * 256 + t];
        __syncthreads();

        const ulonglong2* wss = (const ulonglong2*)(Ws + o * WSTR + p * 32);

        int par = 0;
        for (int s = 0; s < SEQ; s++) {
            float4 xv;
            if (t < 64) xv = ((const float4*)(g_Xp + (size_t)(s * BATCH + b) * HIDDEN))[t];

            const ulonglong2* hsg = ((const ulonglong2*)(hbuf + par * 256)) + p * 8;
            uint64_t accs = 0, accr = 0;
            #pragma unroll
            for (int j = 0; j < 8; j++) {
                ulonglong2 h2 = hsg[j];
                ulonglong2 w2 = wss[j];
                fma2(accs, w2.x, h2.x);
                fma2(accr, wr[j].x, h2.x);
                fma2(accs, w2.y, h2.y);
                fma2(accr, wr[j].y, h2.y);
            }
            part[p * 132 + o]       = lo32(accs) + hi32(accs);
            part[(8 + p) * 132 + o] = lo32(accr) + hi32(accr);
            if (t < 64) ((float4*)xbuf)[t] = xv;
            __syncthreads();

            if (t < 256) {
                int w = t >> 7, oo = t & 127;
                float sum = 0.f;
                #pragma unroll
                for (int q = 0; q < 8; q++) sum += part[(w * 8 + q) * 132 + oo];
                float v = tanhf(sum + xbuf[t]);
                hbuf[(par ^ 1) * 256 + t] = v;
                g_Y[(size_t)(s * BATCH + b) * HIDDEN + t] = __uint_as_float(f2tf32(v));
                if (s == SEQ - 1) g_hlast[b * HIDDEN + t] = v;
                if ((s & 3) == 3) __threadfence();   // release Y rows before publish
            }
            __syncthreads();
            if ((s & 3) == 3 && t == 0) st_rlx(&g_prog[b], (unsigned int)(s + 1));
            par ^= 1;
        }
    } else {
        // ================= gemm consumer: BM128 x BN256 =================
        uint32_t* smbase = (uint32_t*)dynsm;
        const int g = blockIdx.x - 32;
        const int rTile = g >> 5;             // row-tile-major (32 col tiles of 256)
        const int cTile = g & 31;
        const int rowBase = rTile * 128;
        const int colBase = cTile * 256;
        const unsigned int need = (unsigned int)((rTile + 1) * 4);

        if (t < 32) {
            while (ld_acq(&g_prog[t]) < need) __nanosleep(128);
        }
        __syncthreads();

        const int warp = t >> 5, lane = t & 31;
        const int wm = warp & 3, wn = warp >> 2;      // 4(M) x 8(N)
        const int r = lane >> 2, c = lane & 3;
        const uint32_t sm0 = smem_u32(smbase);

        float acc[2][4][4];                            // warp tile 32x32
        #pragma unroll
        for (int mt = 0; mt < 2; mt++)
            #pragma unroll
            for (int nt = 0; nt < 4; nt++)
                #pragma unroll
                for (int i = 0; i < 4; i++) acc[mt][nt][i] = 0.f;

        auto load_stage = [&](int kt, int st) {
            uint32_t abase = sm0 + st * (GSTG * 4);
            uint32_t bbase = abase + 128 * 36 * 4;
            {   // A: 128x32 from g_Y — 1 cpa16 per thread
                int m = t >> 3, k4 = t & 7;
                cpa16(abase + (m * 36 + k4 * 4) * 4,
                      g_Y + (size_t)(rowBase + m) * HIDDEN + kt * 32 + k4 * 4);
            }
            #pragma unroll
            for (int q = 0; q < 2; q++) {   // B: 256x32 from g_Wo — 2 cpa16 per thread
                int lin = q * 1024 + t;
                int n = lin >> 3, k4 = lin & 7;
                cpa16(bbase + (n * 36 + k4 * 4) * 4,
                      g_Wo + (size_t)(colBase + n) * HIDDEN + kt * 32 + k4 * 4);
            }
            asm volatile("cp.async.commit_group;");
        };

        load_stage(0, 0);

        for (int kt = 0; kt < 8; kt++) {
            if (kt < 7) {
                load_stage(kt + 1, (kt + 1) & 1);
                asm volatile("cp.async.wait_group 1;");
            } else {
                asm volatile("cp.async.wait_group 0;");
            }
            __syncthreads();

            const uint32_t* As = smbase + (kt & 1) * GSTG;
            const uint32_t* Bs = As + 128 * 36;

            #pragma unroll
            for (int ks = 0; ks < 4; ks++) {
                uint32_t a[2][4];
                #pragma unroll
                for (int mt = 0; mt < 2; mt++) {
                    int mb = wm * 32 + mt * 16;
                    a[mt][0] = As[(mb + r    ) * 36 + ks * 8 + c    ];
                    a[mt][1] = As[(mb + r + 8) * 36 + ks * 8 + c    ];
                    a[mt][2] = As[(mb + r    ) * 36 + ks * 8 + c + 4];
                    a[mt][3] = As[(mb + r + 8) * 36 + ks * 8 + c + 4];
                }
                #pragma unroll
                for (int nt = 0; nt < 4; nt++) {
                    uint32_t bf[2];
                    int nb = wn * 32 + nt * 8 + r;
                    bf[0] = Bs[nb * 36 + ks * 8 + c    ];
                    bf[1] = Bs[nb * 36 + ks * 8 + c + 4];
                    mma_tf32(acc[0][nt], a[0], bf);
                    mma_tf32(acc[1][nt], a[1], bf);
                }
            }
            __syncthreads();
        }

        // epilogue: bias + predicated STG.64 (cols >= VOCAB are padding)
        #pragma unroll
        for (int mt = 0; mt < 2; mt++) {
            int r0 = rowBase + wm * 32 + mt * 16 + r;
            #pragma unroll
            for (int nt = 0; nt < 4; nt++) {
                int col = colBase + wn * 32 + nt * 8 + c * 2;
                if (col < VOCAB) {
                    float bo0 = bout[col], bo1 = bout[col + 1];
                    float2 v0 = make_float2(acc[mt][nt][0] + bo0, acc[mt][nt][1] + bo1);
                    float2 v1 = make_float2(acc[mt][nt][2] + bo0, acc[mt][nt][3] + bo1);
                    *(float2*)&out[(size_t)r0       * VOCAB + col] = v0;
                    *(float2*)&out[(size_t)(r0 + 8) * VOCAB + col] = v1;
                }
            }
        }
    }
}

// ---------------- K4: h_last tail (exact fp32) ----------------
__global__ void tail_copy(float* __restrict__ out) {
    int t = blockIdx.x * blockDim.x + threadIdx.x;   // 0..8191
    out[(size_t)NROW * VOCAB + t] = g_hlast[t];
}

// ---------------- launch ----------------
extern "C" void kernel_launch(void* const* d_in, const int* in_sizes, int n_in,
                              void* d_out, int out_size) {
    const int*   X     = (const int*)  d_in[0];
    const float* h0    = (const float*)d_in[1];
    const float* W_ih  = (const float*)d_in[2];
    const float* b_ih  = (const float*)d_in[3];
    const float* W_hh  = (const float*)d_in[4];
    const float* b_hh  = (const float*)d_in[5];
    const float* W_out = (const float*)d_in[6];
    const float* b_out = (const float*)d_in[7];
    float* out = (float*)d_out;

    cudaFuncSetAttribute(fused_scan_gemm, cudaFuncAttributeMaxDynamicSharedMemorySize, FUSED_SMEM);

    // prep: 8192 gather blocks + 2048 round blocks (transpose eliminated)
    prep<<<NROW + (VPAD * 64) / 256, 256>>>(X, W_ih, b_ih, b_hh, W_out);
    // 32 scan blocks first, then 64x32 gemm tiles (row-tile-major, BN256)
    fused_scan_gemm<<<32 + 64 * 32, 1024, FUSED_SMEM>>>(W_hh, h0, b_out, out);
    if ((long long)out_size >= (long long)NROW * VOCAB + BATCH * HIDDEN)
        tail_copy<<<BATCH, HIDDEN>>>(out);
}

// round 12
// speedup vs baseline: 1.4201x; 1.4201x over previous
#include <cuda_runtime.h>
#include <cstdint>

#define VOCAB  8000
#define VPAD   8192               // g_Wo rows padded (zero-filled)
#define HIDDEN 256
#define BATCH  32
#define SEQ    256
#define NROW   (SEQ * BATCH)      // 8192 output rows

// ---------------- scratch (device globals: allocation-free) ----------------
__device__ float g_Xp[NROW * HIDDEN];    // gathered emb + b_ih + b_hh
__device__ float g_Y [NROW * HIDDEN];    // RNN hidden outputs (tf32-rounded)
__device__ float g_Wo[VPAD * HIDDEN];    // W_out pre-rounded to tf32, zero-padded
__device__ float g_hlast[BATCH * HIDDEN];// exact fp32 final hidden state
__device__ unsigned int g_prog[BATCH];   // per-batch completed-step counter

extern __shared__ unsigned char dynsm[];

// ---------------- helpers ----------------
__device__ __forceinline__ uint32_t smem_u32(const void* p) {
    uint32_t a;
    asm("{ .reg .u64 t; cvta.to.shared.u64 t, %1; cvt.u32.u64 %0, t; }"
        : "=r"(a) : "l"(p));
    return a;
}
__device__ __forceinline__ uint32_t f2tf32(float f) {
    uint32_t r; asm("cvt.rna.tf32.f32 %0, %1;" : "=r"(r) : "f"(f)); return r;
}
__device__ __forceinline__ void fma2(uint64_t& d, uint64_t a, uint64_t b) {
    asm("fma.rn.f32x2 %0, %1, %2, %0;" : "+l"(d) : "l"(a), "l"(b));
}
__device__ __forceinline__ float lo32(uint64_t v) { return __uint_as_float((uint32_t)v); }
__device__ __forceinline__ float hi32(uint64_t v) { return __uint_as_float((uint32_t)(v >> 32)); }
__device__ __forceinline__ void cpa16(uint32_t dst, const void* src) {
    asm volatile("cp.async.cg.shared.global [%0], [%1], 16;" :: "r"(dst), "l"(src));
}
__device__ __forceinline__ unsigned int ld_acq(const unsigned int* p) {
    unsigned int v;
    asm volatile("ld.acquire.gpu.u32 %0, [%1];" : "=r"(v) : "l"(p) : "memory");
    return v;
}
__device__ __forceinline__ void st_rlx(unsigned int* p, unsigned int v) {
    asm volatile("st.relaxed.gpu.u32 [%0], %1;" :: "l"(p), "r"(v) : "memory");
}

// ---------------- K1: fused prep (measured 22.9us in R11) ----------------
// Blocks 0..8191: Xp[r][i] = W_ih[i][X[b][s]] + b_ih[i] + b_hh[i]
// Blocks 8192..:  pre-round W_out to tf32 (zero-pad rows >= VOCAB); zero g_prog.
__global__ void __launch_bounds__(256)
prep(const int* __restrict__ X, const float* __restrict__ Wih,
     const float* __restrict__ b_ih, const float* __restrict__ b_hh,
     const float* __restrict__ Wout) {
    const int t = threadIdx.x;
    if (blockIdx.x < NROW) {
        const int r = blockIdx.x;
        if (r == 0 && t < BATCH) g_prog[t] = 0;
        const int s = r >> 5, b = r & 31;
        const int v = X[b * SEQ + s];                 // broadcast load
        float e = Wih[(size_t)t * VOCAB + v] + b_ih[t] + b_hh[t];
        g_Xp[(size_t)r * HIDDEN + t] = e;
    } else {
        int i = (blockIdx.x - NROW) * 256 + t;        // over VPAD*64 float4s
        int row = i >> 6;
        uint4 u = make_uint4(0u, 0u, 0u, 0u);
        if (row < VOCAB) {
            float4 f = ((const float4*)Wout)[i];
            u = make_uint4(f2tf32(f.x), f2tf32(f.y), f2tf32(f.z), f2tf32(f.w));
        }
        ((uint4*)g_Wo)[i] = u;
    }
}

// ---------------- K2: FUSED scan + GEMM (persistent overlap) ----------------
// Blocks 0..31: rnn scan (scan6, proven 264us), publishing g_prog every 4 steps.
// Blocks 32..4127: GEMM BM128 x BN128, row-tile-major. Warp tile 32x16
//   (acc=16 regs -- HARD LIMIT at 1024 thr, see R5/R11 spills), but LDS traffic
//   halved vs R10 via k-slot pairing: fragment slot c <- smem col 2c, slot
//   c+4 <- col 2c+1 for BOTH A and B (k-permutation invariance) -> uint2
//   loads; smem row stride 40 makes the 16-lane LDS.64 phase hit banks
//   8r+2c, all distinct -> conflict-free. 6 LDS.64 per 4 mma (was 12 LDS.32).
#define WSTR      260
#define HB_OFF    (128 * WSTR)                  // hbuf: [2][256]
#define PART_OFF  (HB_OFF + 512)                // part: [16][132]
#define XBUF_OFF  (PART_OFF + 2112)             // xbuf: [256]
#define FUSED_SMEM ((XBUF_OFF + 256) * 4)       // 144,640 B

#define GROW  40                                 // gemm smem row stride (words)
#define GSTG  (128 * GROW + 128 * GROW)          // 10240 u32 per stage (40KB; x2=80KB)

__device__ __forceinline__ void mma_tf32(float* d, const uint32_t* a, const uint32_t* b) {
    asm volatile(
        "mma.sync.aligned.m16n8k8.row.col.f32.tf32.tf32.f32 "
        "{%0,%1,%2,%3}, {%4,%5,%6,%7}, {%8,%9}, {%0,%1,%2,%3};"
        : "+f"(d[0]), "+f"(d[1]), "+f"(d[2]), "+f"(d[3])
        : "r"(a[0]), "r"(a[1]), "r"(a[2]), "r"(a[3]), "r"(b[0]), "r"(b[1]));
}

__global__ void __launch_bounds__(1024, 1)
fused_scan_gemm(const float* __restrict__ Whh, const float* __restrict__ h0,
                const float* __restrict__ bout, float* __restrict__ out) {
    const int t = threadIdx.x;

    if (blockIdx.x < 32) {
        // ================= scan (scan6 verbatim) =================
        float* Ws   = (float*)dynsm;          // [128][260]
        float* hbuf = Ws + HB_OFF;
        float* part = Ws + PART_OFF;
        float* xbuf = Ws + XBUF_OFF;

        const int b = blockIdx.x;
        const int o = t & 127;
        const int p = t >> 7;

        for (int i = t; i < 128 * 256; i += 1024) {
            int r = i >> 8, c = i & 255;
            Ws[r * WSTR + c] = Whh[r * 256 + c];
        }
        ulonglong2 wr[8];
        {
            const ulonglong2* wsrc = (const ulonglong2*)(Whh + (size_t)(128 + o) * 256 + p * 32);
            #pragma unroll
            for (int i = 0; i < 8; i++) wr[i] = wsrc[i];
        }
        if (t < 256) hbuf[t] = h0[b * 256 + t];
        __syncthreads();

        const ulonglong2* wss = (const ulonglong2*)(Ws + o * WSTR + p * 32);

        int par = 0;
        for (int s = 0; s < SEQ; s++) {
            float4 xv;
            if (t < 64) xv = ((const float4*)(g_Xp + (size_t)(s * BATCH + b) * HIDDEN))[t];

            const ulonglong2* hsg = ((const ulonglong2*)(hbuf + par * 256)) + p * 8;
            uint64_t accs = 0, accr = 0;
            #pragma unroll
            for (int j = 0; j < 8; j++) {
                ulonglong2 h2 = hsg[j];
                ulonglong2 w2 = wss[j];
                fma2(accs, w2.x, h2.x);
                fma2(accr, wr[j].x, h2.x);
                fma2(accs, w2.y, h2.y);
                fma2(accr, wr[j].y, h2.y);
            }
            part[p * 132 + o]       = lo32(accs) + hi32(accs);
            part[(8 + p) * 132 + o] = lo32(accr) + hi32(accr);
            if (t < 64) ((float4*)xbuf)[t] = xv;
            __syncthreads();

            if (t < 256) {
                int w = t >> 7, oo = t & 127;
                float sum = 0.f;
                #pragma unroll
                for (int q = 0; q < 8; q++) sum += part[(w * 8 + q) * 132 + oo];
                float v = tanhf(sum + xbuf[t]);
                hbuf[(par ^ 1) * 256 + t] = v;
                g_Y[(size_t)(s * BATCH + b) * HIDDEN + t] = __uint_as_float(f2tf32(v));
                if (s == SEQ - 1) g_hlast[b * HIDDEN + t] = v;
                if ((s & 3) == 3) __threadfence();   // release Y rows before publish
            }
            __syncthreads();
            if ((s & 3) == 3 && t == 0) st_rlx(&g_prog[b], (unsigned int)(s + 1));
            par ^= 1;
        }
    } else {
        // ================= gemm consumer: BM128 x BN128, paired LDS.64 =================
        uint32_t* smbase = (uint32_t*)dynsm;
        const int g = blockIdx.x - 32;
        const int rTile = g >> 6;             // row-tile-major (64 col tiles of 128)
        const int cTile = g & 63;
        const int rowBase = rTile * 128;
        const int colBase = cTile * 128;
        const unsigned int need = (unsigned int)((rTile + 1) * 4);

        if (t < 32) {
            while (ld_acq(&g_prog[t]) < need) __nanosleep(128);
        }
        __syncthreads();

        const int warp = t >> 5, lane = t & 31;
        const int wm = warp & 3, wn = warp >> 2;      // 4(M) x 8(N)
        const int r = lane >> 2, c = lane & 3;
        const uint32_t sm0 = smem_u32(smbase);

        float acc[2][2][4];                            // warp tile 32x16: 16 regs MAX
        #pragma unroll
        for (int mt = 0; mt < 2; mt++)
            #pragma unroll
            for (int nt = 0; nt < 2; nt++)
                #pragma unroll
                for (int i = 0; i < 4; i++) acc[mt][nt][i] = 0.f;

        auto load_stage = [&](int kt, int st) {
            uint32_t abase = sm0 + st * (GSTG * 4);
            uint32_t bbase = abase + 128 * GROW * 4;
            {   // A: 128x32 from g_Y — 1 cpa16 per thread
                int m = t >> 3, k4 = t & 7;
                cpa16(abase + (m * GROW + k4 * 4) * 4,
                      g_Y + (size_t)(rowBase + m) * HIDDEN + kt * 32 + k4 * 4);
            }
            {   // B: 128x32 from g_Wo — 1 cpa16 per thread
                int n = t >> 3, k4 = t & 7;
                cpa16(bbase + (n * GROW + k4 * 4) * 4,
                      g_Wo + (size_t)(colBase + n) * HIDDEN + kt * 32 + k4 * 4);
            }
            asm volatile("cp.async.commit_group;");
        };

        load_stage(0, 0);

        for (int kt = 0; kt < 8; kt++) {
            if (kt < 7) {
                load_stage(kt + 1, (kt + 1) & 1);
                asm volatile("cp.async.wait_group 1;");
            } else {
                asm volatile("cp.async.wait_group 0;");
            }
            __syncthreads();

            const uint32_t* As = smbase + (kt & 1) * GSTG;
            const uint32_t* Bs = As + 128 * GROW;

            #pragma unroll
            for (int ks = 0; ks < 4; ks++) {
                // k-slot pairing: fragment slot c <- col 2c, slot c+4 <- col 2c+1
                uint32_t a[2][4], bf[2][2];
                #pragma unroll
                for (int mt = 0; mt < 2; mt++) {
                    int mb = wm * 32 + mt * 16;
                    uint2 lo = *(const uint2*)&As[(mb + r    ) * GROW + ks * 8 + 2 * c];
                    uint2 hi = *(const uint2*)&As[(mb + r + 8) * GROW + ks * 8 + 2 * c];
                    a[mt][0] = lo.x;  a[mt][2] = lo.y;   // row r:   k slots c, c+4
                    a[mt][1] = hi.x;  a[mt][3] = hi.y;   // row r+8: k slots c, c+4
                }
                #pragma unroll
                for (int nt = 0; nt < 2; nt++) {
                    int nb = wn * 16 + nt * 8 + r;
                    uint2 bv = *(const uint2*)&Bs[nb * GROW + ks * 8 + 2 * c];
                    bf[nt][0] = bv.x;  bf[nt][1] = bv.y;
                }
                #pragma unroll
                for (int mt = 0; mt < 2; mt++)
                    #pragma unroll
                    for (int nt = 0; nt < 2; nt++)
                        mma_tf32(acc[mt][nt], a[mt], bf[nt]);
            }
            __syncthreads();
        }

        // epilogue: bias + predicated STG.64 (cols >= VOCAB are padding)
        #pragma unroll
        for (int mt = 0; mt < 2; mt++) {
            int r0 = rowBase + wm * 32 + mt * 16 + r;
            #pragma unroll
            for (int nt = 0; nt < 2; nt++) {
                int col = colBase + wn * 16 + nt * 8 + c * 2;
                if (col < VOCAB) {
                    float bo0 = bout[col], bo1 = bout[col + 1];
                    float2 v0 = make_float2(acc[mt][nt][0] + bo0, acc[mt][nt][1] + bo1);
                    float2 v1 = make_float2(acc[mt][nt][2] + bo0, acc[mt][nt][3] + bo1);
                    *(float2*)&out[(size_t)r0       * VOCAB + col] = v0;
                    *(float2*)&out[(size_t)(r0 + 8) * VOCAB + col] = v1;
                }
            }
        }
    }
}

// ---------------- K4: h_last tail (exact fp32) ----------------
__global__ void tail_copy(float* __restrict__ out) {
    int t = blockIdx.x * blockDim.x + threadIdx.x;   // 0..8191
    out[(size_t)NROW * VOCAB + t] = g_hlast[t];
}

// ---------------- launch ----------------
extern "C" void kernel_launch(void* const* d_in, const int* in_sizes, int n_in,
                              void* d_out, int out_size) {
    const int*   X     = (const int*)  d_in[0];
    const float* h0    = (const float*)d_in[1];
    const float* W_ih  = (const float*)d_in[2];
    const float* b_ih  = (const float*)d_in[3];
    const float* W_hh  = (const float*)d_in[4];
    const float* b_hh  = (const float*)d_in[5];
    const float* W_out = (const float*)d_in[6];
    const float* b_out = (const float*)d_in[7];
    float* out = (float*)d_out;

    cudaFuncSetAttribute(fused_scan_gemm, cudaFuncAttributeMaxDynamicSharedMemorySize, FUSED_SMEM);

    prep<<<NROW + (VPAD * 64) / 256, 256>>>(X, W_ih, b_ih, b_hh, W_out);
    // 32 scan blocks first, then 64x64 gemm tiles (row-tile-major)
    fused_scan_gemm<<<32 + 64 * 64, 1024, FUSED_SMEM>>>(W_hh, h0, b_out, out);
    if ((long long)out_size >= (long long)NROW * VOCAB + BATCH * HIDDEN)
        tail_copy<<<BATCH, HIDDEN>>>(out);
}